// round 1
// baseline (speedup 1.0000x reference)
#include <cuda_runtime.h>
#include <math.h>

#define DD   1024
#define NH   16
#define HDIM 64
#define BB   2
#define LL   2048
#define MTOK (BB*LL)   // 4096

// ---------------- scratch (device globals; no allocations allowed) ----------
__device__ float g_Wc[3][DD*DD];            // combined weights W^T @ R  (12 MB)
__device__ float g_Q[BB*NH*LL*HDIM];        // 16 MB  [b][h][l][d], pre-scaled
__device__ float g_K[BB*NH*LL*HDIM];        // 16 MB
__device__ float g_V[BB*NH*LL*HDIM];        // 16 MB
__device__ float g_O[MTOK*DD];              // attention out in (B,L,D), 16 MB

// ============================================================================
// Kernel 1: Wc[z] = W[z]^T @ R     (1024x1024 = 1024x1024^T * 1024x1024)
// TN GEMM, tile 64x64x16, 256 threads, 4x4 microtile.
// ============================================================================
__global__ __launch_bounds__(256) void combine_weights_kernel(
    const float* __restrict__ Wq, const float* __restrict__ Wk,
    const float* __restrict__ Wv, const float* __restrict__ R)
{
    const float* W = (blockIdx.z == 0) ? Wq : ((blockIdx.z == 1) ? Wk : Wv);
    float* C = g_Wc[blockIdx.z];

    __shared__ float As[16][64];   // As[kk][ii] = W[(kt+kk)*D + i0+ii]  (= W^T[i][k])
    __shared__ float Bs[16][64];   // Bs[kk][jj] = R[(kt+kk)*D + j0+jj]

    const int tid = threadIdx.x;
    const int tx = tid & 15, ty = tid >> 4;
    const int i0 = blockIdx.y * 64, j0 = blockIdx.x * 64;
    const int lkk = tid >> 4, lc4 = (tid & 15) * 4;

    float acc[4][4] = {};

    for (int kt = 0; kt < DD; kt += 16) {
        *(float4*)&As[lkk][lc4] = *(const float4*)&W[(kt + lkk) * DD + i0 + lc4];
        *(float4*)&Bs[lkk][lc4] = *(const float4*)&R[(kt + lkk) * DD + j0 + lc4];
        __syncthreads();
        #pragma unroll
        for (int k = 0; k < 16; k++) {
            float4 a4 = *(float4*)&As[k][ty * 4];
            float4 b4 = *(float4*)&Bs[k][tx * 4];
            float av[4] = {a4.x, a4.y, a4.z, a4.w};
            float bv[4] = {b4.x, b4.y, b4.z, b4.w};
            #pragma unroll
            for (int i = 0; i < 4; i++)
                #pragma unroll
                for (int j = 0; j < 4; j++)
                    acc[i][j] += av[i] * bv[j];
        }
        __syncthreads();
    }
    #pragma unroll
    for (int i = 0; i < 4; i++) {
        float4 v = {acc[i][0], acc[i][1], acc[i][2], acc[i][3]};
        *(float4*)&C[(i0 + ty * 4 + i) * DD + j0 + tx * 4] = v;
    }
}

// ============================================================================
// Kernel 2: P = X @ Wc[z], scattered into head layout [b][h][l][d].
// z=0 -> Q (scaled by entangle[h]/8), z=1 -> K, z=2 -> V.
// NN GEMM, tile 64x64x16. blockIdx.x == head (N tile of 64 == one head).
// ============================================================================
__global__ __launch_bounds__(256) void qkv_proj_kernel(
    const float* __restrict__ X, const float* __restrict__ ent)
{
    const int z = blockIdx.z;
    const float* Wc = g_Wc[z];
    float* Out = (z == 0) ? g_Q : ((z == 1) ? g_K : g_V);

    __shared__ float As[64][17];   // As[ii][kk] = X[(m0+ii)*D + kt+kk]
    __shared__ float Bs[16][64];   // Bs[kk][jj] = Wc[(kt+kk)*D + j0+jj]

    const int tid = threadIdx.x;
    const int tx = tid & 15, ty = tid >> 4;
    const int m0 = blockIdx.y * 64;
    const int h  = blockIdx.x;
    const int j0 = h * 64;
    const float scale = (z == 0) ? (ent[h] * 0.125f) : 1.0f;

    const int arow = tid >> 2, akc = (tid & 3) * 4;
    const int lkk = tid >> 4, lc4 = (tid & 15) * 4;

    float acc[4][4] = {};

    for (int kt = 0; kt < DD; kt += 16) {
        float4 av4 = *(const float4*)&X[(m0 + arow) * DD + kt + akc];
        As[arow][akc + 0] = av4.x;
        As[arow][akc + 1] = av4.y;
        As[arow][akc + 2] = av4.z;
        As[arow][akc + 3] = av4.w;
        *(float4*)&Bs[lkk][lc4] = *(const float4*)&Wc[(kt + lkk) * DD + j0 + lc4];
        __syncthreads();
        #pragma unroll
        for (int k = 0; k < 16; k++) {
            float av[4];
            #pragma unroll
            for (int i = 0; i < 4; i++) av[i] = As[ty * 4 + i][k];
            float4 b4 = *(float4*)&Bs[k][tx * 4];
            float bv[4] = {b4.x, b4.y, b4.z, b4.w};
            #pragma unroll
            for (int i = 0; i < 4; i++)
                #pragma unroll
                for (int j = 0; j < 4; j++)
                    acc[i][j] += av[i] * bv[j];
        }
        __syncthreads();
    }

    const int b = m0 >> 11;            // L = 2048; a 64-row tile never crosses b
    #pragma unroll
    for (int i = 0; i < 4; i++) {
        int m = m0 + ty * 4 + i;
        int l = m & (LL - 1);
        float4 v = {acc[i][0] * scale, acc[i][1] * scale,
                    acc[i][2] * scale, acc[i][3] * scale};
        *(float4*)&Out[(((size_t)(b * NH + h)) * LL + l) * HDIM + tx * 4] = v;
    }
}

// ============================================================================
// Kernel 3: flash attention (fp32). grid=(L/128, B*H), 128 threads.
// Each thread owns one query row: q[64] + acc[64] in registers,
// K/V tiles of 32 keys staged in smem, online softmax.
// Scores are pre-scaled (scale folded into Q).
// ============================================================================
__global__ __launch_bounds__(128) void flash_attn_kernel()
{
    const int bh = blockIdx.y;
    const int b = bh >> 4, h = bh & 15;
    const int tid = threadIdx.x;
    const int qrow = blockIdx.x * 128 + tid;

    const size_t head_off = ((size_t)(b * NH + h)) * LL * HDIM;
    const float* Qb = g_Q + head_off;
    const float* Kb = g_K + head_off;
    const float* Vb = g_V + head_off;

    __shared__ float Ksm[32][64];
    __shared__ float Vsm[32][64];

    float q[64];
    #pragma unroll
    for (int k4 = 0; k4 < 16; k4++) {
        float4 v = *(const float4*)&Qb[(size_t)qrow * HDIM + k4 * 4];
        q[k4 * 4 + 0] = v.x; q[k4 * 4 + 1] = v.y;
        q[k4 * 4 + 2] = v.z; q[k4 * 4 + 3] = v.w;
    }

    float acc[64] = {};
    float mval = -1e30f, lval = 0.0f;

    for (int k0 = 0; k0 < LL; k0 += 32) {
        // cooperative flat copy of 32x64 K and V tiles
        const float4* Kg = (const float4*)(Kb + (size_t)k0 * HDIM);
        const float4* Vg = (const float4*)(Vb + (size_t)k0 * HDIM);
        float4* K4 = (float4*)&Ksm[0][0];
        float4* V4 = (float4*)&Vsm[0][0];
        #pragma unroll
        for (int r = 0; r < 4; r++) {
            K4[tid + 128 * r] = Kg[tid + 128 * r];
            V4[tid + 128 * r] = Vg[tid + 128 * r];
        }
        __syncthreads();

        float s[32];
        #pragma unroll
        for (int j = 0; j < 32; j++) {
            float sum = 0.0f;
            #pragma unroll
            for (int k4 = 0; k4 < 16; k4++) {
                float4 kv = *(float4*)&Ksm[j][k4 * 4];
                sum += q[k4 * 4 + 0] * kv.x + q[k4 * 4 + 1] * kv.y
                     + q[k4 * 4 + 2] * kv.z + q[k4 * 4 + 3] * kv.w;
            }
            s[j] = sum;
        }

        float tmax = s[0];
        #pragma unroll
        for (int j = 1; j < 32; j++) tmax = fmaxf(tmax, s[j]);
        float newm = fmaxf(mval, tmax);
        float corr = __expf(mval - newm);
        lval *= corr;
        #pragma unroll
        for (int d = 0; d < 64; d++) acc[d] *= corr;

        #pragma unroll
        for (int j = 0; j < 32; j++) {
            float p = __expf(s[j] - newm);
            lval += p;
            #pragma unroll
            for (int d4 = 0; d4 < 16; d4++) {
                float4 vv = *(float4*)&Vsm[j][d4 * 4];
                acc[d4 * 4 + 0] += p * vv.x;
                acc[d4 * 4 + 1] += p * vv.y;
                acc[d4 * 4 + 2] += p * vv.z;
                acc[d4 * 4 + 3] += p * vv.w;
            }
        }
        mval = newm;
        __syncthreads();
    }

    const float inv = 1.0f / lval;
    float* Ob = g_O + ((size_t)b * LL + qrow) * DD + h * HDIM;
    #pragma unroll
    for (int d4 = 0; d4 < 16; d4++) {
        float4 v = {acc[d4 * 4 + 0] * inv, acc[d4 * 4 + 1] * inv,
                    acc[d4 * 4 + 2] * inv, acc[d4 * 4 + 3] * inv};
        *(float4*)&Ob[d4 * 4] = v;
    }
}

// ============================================================================
// Kernel 4: Y = O @ Wo^T.   NT GEMM, tile 64x64x16.
// ============================================================================
__global__ __launch_bounds__(256) void out_proj_kernel(
    const float* __restrict__ Wo, float* __restrict__ Y)
{
    __shared__ float As[64][17];   // As[ii][kk] = O[(m0+ii)*D + kt+kk]
    __shared__ float Bs[64][17];   // Bs[jj][kk] = Wo[(j0+jj)*D + kt+kk]

    const int tid = threadIdx.x;
    const int tx = tid & 15, ty = tid >> 4;
    const int m0 = blockIdx.y * 64, j0 = blockIdx.x * 64;
    const int row = tid >> 2, kc = (tid & 3) * 4;

    float acc[4][4] = {};

    for (int kt = 0; kt < DD; kt += 16) {
        float4 a4 = *(const float4*)&g_O[(size_t)(m0 + row) * DD + kt + kc];
        As[row][kc + 0] = a4.x; As[row][kc + 1] = a4.y;
        As[row][kc + 2] = a4.z; As[row][kc + 3] = a4.w;
        float4 b4 = *(const float4*)&Wo[(size_t)(j0 + row) * DD + kt + kc];
        Bs[row][kc + 0] = b4.x; Bs[row][kc + 1] = b4.y;
        Bs[row][kc + 2] = b4.z; Bs[row][kc + 3] = b4.w;
        __syncthreads();
        #pragma unroll
        for (int k = 0; k < 16; k++) {
            float av[4], bv[4];
            #pragma unroll
            for (int i = 0; i < 4; i++) av[i] = As[ty * 4 + i][k];
            #pragma unroll
            for (int j = 0; j < 4; j++) bv[j] = Bs[tx * 4 + j][k];
            #pragma unroll
            for (int i = 0; i < 4; i++)
                #pragma unroll
                for (int j = 0; j < 4; j++)
                    acc[i][j] += av[i] * bv[j];
        }
        __syncthreads();
    }
    #pragma unroll
    for (int i = 0; i < 4; i++) {
        float4 v = {acc[i][0], acc[i][1], acc[i][2], acc[i][3]};
        *(float4*)&Y[(size_t)(m0 + ty * 4 + i) * DD + j0 + tx * 4] = v;
    }
}

// ============================================================================
// launch
// Inputs (metadata order): 0=inputs(B,L,D) 1=rotation(D,D) 2=entangle(H)
//                          3=Wq 4=Wk 5=Wv 6=Wo  (all (D,D) fp32)
// Output: (B,L,D) fp32
// ============================================================================
extern "C" void kernel_launch(void* const* d_in, const int* in_sizes, int n_in,
                              void* d_out, int out_size)
{
    const float* X   = (const float*)d_in[0];
    const float* R   = (const float*)d_in[1];
    const float* ent = (const float*)d_in[2];
    const float* Wq  = (const float*)d_in[3];
    const float* Wk  = (const float*)d_in[4];
    const float* Wv  = (const float*)d_in[5];
    const float* Wo  = (const float*)d_in[6];
    float* Y = (float*)d_out;

    combine_weights_kernel<<<dim3(16, 16, 3), 256>>>(Wq, Wk, Wv, R);
    qkv_proj_kernel<<<dim3(NH, MTOK / 64, 3), 256>>>(X, ent);
    flash_attn_kernel<<<dim3(LL / 128, BB * NH), 128>>>();
    out_proj_kernel<<<dim3(DD / 64, MTOK / 64), 256>>>(Wo, Y);
}